// round 1
// baseline (speedup 1.0000x reference)
#include <cuda_runtime.h>

// ---------------- problem constants ----------------
#define PN    8192
#define WD    256
#define HD    256
#define TANXc 0.5f
#define TANYc 0.5f
#define FXc   256.0f   // W / (2*TANX)
#define FYc   256.0f   // H / (2*TANY)

typedef unsigned long long u64;

// ---------------- scratch (__device__ globals: no allocation allowed) ----------------
__device__ float4 g_pe_u[PN];   // unsorted: mean2d.x, mean2d.y, ext_x, ext_y
__device__ float4 g_co_u[PN];   // unsorted: conic A,B,C, opacity
__device__ float4 g_cl_u[PN];   // unsorted: color r,g,b, pad
__device__ u64    g_keys[PN];   // (depth_bits << 32) | idx
__device__ float4 g_pe[PN];     // sorted copies
__device__ float4 g_co[PN];
__device__ float4 g_cl[PN];

// ---------------- preprocess: per-gaussian projection / conic / AABB ----------------
__global__ void preprocess_kernel(const float* __restrict__ means,
                                  const float* __restrict__ cols,
                                  const float* __restrict__ ops,
                                  const float* __restrict__ scales,
                                  const float* __restrict__ rots,
                                  const float* __restrict__ Vm,
                                  const float* __restrict__ Pr)
{
    int i = blockIdx.x * blockDim.x + threadIdx.x;
    if (i >= PN) return;

    float mx = means[3*i+0], my = means[3*i+1], mz = means[3*i+2];

    // p_view = hom @ V  (row-vector convention)
    float pv0 = mx*Vm[0] + my*Vm[4] + mz*Vm[8]  + Vm[12];
    float pv1 = mx*Vm[1] + my*Vm[5] + mz*Vm[9]  + Vm[13];
    float pv2 = mx*Vm[2] + my*Vm[6] + mz*Vm[10] + Vm[14];

    // p_hom = hom @ projmatrix
    float ph0 = mx*Pr[0] + my*Pr[4] + mz*Pr[8]  + Pr[12];
    float ph1 = mx*Pr[1] + my*Pr[5] + mz*Pr[9]  + Pr[13];
    float ph3 = mx*Pr[3] + my*Pr[7] + mz*Pr[11] + Pr[15];
    float invw = 1.0f / (ph3 + 1e-7f);
    float m2x = ((ph0*invw + 1.0f) * (float)WD - 1.0f) * 0.5f;
    float m2y = ((ph1*invw + 1.0f) * (float)HD - 1.0f) * 0.5f;

    // quaternion -> rotation
    float qr = rots[4*i+0], qx = rots[4*i+1], qy = rots[4*i+2], qz = rots[4*i+3];
    float qn = sqrtf(qr*qr + qx*qx + qy*qy + qz*qz);
    qr /= qn; qx /= qn; qy /= qn; qz /= qn;
    float R[3][3];
    R[0][0] = 1.0f - 2.0f*(qy*qy + qz*qz); R[0][1] = 2.0f*(qx*qy - qr*qz); R[0][2] = 2.0f*(qx*qz + qr*qy);
    R[1][0] = 2.0f*(qx*qy + qr*qz); R[1][1] = 1.0f - 2.0f*(qx*qx + qz*qz); R[1][2] = 2.0f*(qy*qz - qr*qx);
    R[2][0] = 2.0f*(qx*qz - qr*qy); R[2][1] = 2.0f*(qy*qz + qr*qx); R[2][2] = 1.0f - 2.0f*(qx*qx + qy*qy);

    float s0 = scales[3*i+0], s1 = scales[3*i+1], s2 = scales[3*i+2];
    float sq0 = s0*s0, sq1 = s1*s1, sq2 = s2*s2;   // SCALE_MOD = 1

    // Sigma = R diag(s^2) R^T
    float Sg[3][3];
    #pragma unroll
    for (int r = 0; r < 3; r++)
        #pragma unroll
        for (int c = 0; c < 3; c++)
            Sg[r][c] = R[r][0]*sq0*R[c][0] + R[r][1]*sq1*R[c][1] + R[r][2]*sq2*R[c][2];

    // cov_cam = Rv^T Sigma Rv,  Rv = V[:3,:3]
    float Mt[3][3], Cc[3][3];
    #pragma unroll
    for (int r = 0; r < 3; r++)
        #pragma unroll
        for (int k = 0; k < 3; k++)
            Mt[r][k] = Vm[0*4+r]*Sg[0][k] + Vm[1*4+r]*Sg[1][k] + Vm[2*4+r]*Sg[2][k];
    #pragma unroll
    for (int r = 0; r < 3; r++)
        #pragma unroll
        for (int l = 0; l < 3; l++)
            Cc[r][l] = Mt[r][0]*Vm[0*4+l] + Mt[r][1]*Vm[1*4+l] + Mt[r][2]*Vm[2*4+l];

    // Jacobian with clipped tx,ty
    float tz  = pv2;
    float itz = 1.0f / tz;
    float limx = 1.3f * TANXc, limy = 1.3f * TANYc;
    float txc = fminf(limx, fmaxf(-limx, pv0*itz)) * tz;
    float tyc = fminf(limy, fmaxf(-limy, pv1*itz)) * tz;
    float J00 = FXc*itz, J02 = -FXc*txc*itz*itz;
    float J11 = FYc*itz, J12 = -FYc*tyc*itz*itz;

    // cov2d = J Cc J^T
    float T00 = J00*Cc[0][0] + J02*Cc[2][0];
    float T01 = J00*Cc[0][1] + J02*Cc[2][1];
    float T02 = J00*Cc[0][2] + J02*Cc[2][2];
    float T11 = J11*Cc[1][1] + J12*Cc[2][1];
    float T12 = J11*Cc[1][2] + J12*Cc[2][2];
    float c00 = T00*J00 + T02*J02;
    float c01 = T01*J11 + T02*J12;
    float c11 = T11*J11 + T12*J12;

    float a = c00 + 0.3f, b = c01, c = c11 + 0.3f;
    float det  = a*c - b*b;
    float idet = 1.0f / det;
    float A  = c*idet, B = -b*idet, C2 = a*idet;   // conic = [c,-b,a]/det

    float o   = ops[i];
    // alpha >= 1/255  <=>  Q(d) <= tau = 2*ln(255*o).  AABB half-extent = sqrt(tau * Sigma2d_diag)
    float tau = 2.0f * logf(255.0f * o);
    float tq  = fmaxf(tau, 0.0f);
    float ex  = sqrtf(tq * a) + 1.0f;   // +1px margin vs float rounding
    float ey  = sqrtf(tq * c) + 1.0f;
    if (tau <= 0.0f) { ex = -1e30f; ey = -1e30f; }  // never visible

    g_pe_u[i] = make_float4(m2x, m2y, ex, ey);
    g_co_u[i] = make_float4(A, B, C2, o);
    g_cl_u[i] = make_float4(cols[3*i+0], cols[3*i+1], cols[3*i+2], 0.0f);
    // depth = p_view.z > 0 here -> float bits monotonic as unsigned
    g_keys[i] = ((u64)__float_as_uint(pv2) << 32) | (unsigned)i;
}

// ---------------- bitonic sort of 8192 u64 keys (hybrid smem/global) ----------------
__global__ void bitonic_local_sort()
{
    __shared__ u64 sk[2048];
    int base = blockIdx.x * 2048;
    int t = threadIdx.x;
    sk[t]        = g_keys[base + t];
    sk[t + 1024] = g_keys[base + t + 1024];
    __syncthreads();
    for (int k = 2; k <= 2048; k <<= 1) {
        for (int j = k >> 1; j > 0; j >>= 1) {
            int i  = ((t & ~(j - 1)) << 1) | (t & (j - 1));
            bool up = (((base + i) & k) == 0);
            u64 x = sk[i], y = sk[i | j];
            if ((x > y) == up) { sk[i] = y; sk[i | j] = x; }
            __syncthreads();
        }
    }
    g_keys[base + t]        = sk[t];
    g_keys[base + t + 1024] = sk[t + 1024];
}

__global__ void bitonic_global(int k, int j)
{
    int t = blockIdx.x * blockDim.x + threadIdx.x;   // PN/2 threads
    int i = ((t & ~(j - 1)) << 1) | (t & (j - 1));
    bool up = ((i & k) == 0);
    u64 x = g_keys[i], y = g_keys[i | j];
    if ((x > y) == up) { g_keys[i] = y; g_keys[i | j] = x; }
}

__global__ void bitonic_local_merge(int k)
{
    __shared__ u64 sk[2048];
    int base = blockIdx.x * 2048;
    int t = threadIdx.x;
    sk[t]        = g_keys[base + t];
    sk[t + 1024] = g_keys[base + t + 1024];
    __syncthreads();
    for (int j = 1024; j > 0; j >>= 1) {
        int i  = ((t & ~(j - 1)) << 1) | (t & (j - 1));
        bool up = (((base + i) & k) == 0);
        u64 x = sk[i], y = sk[i | j];
        if ((x > y) == up) { sk[i] = y; sk[i | j] = x; }
        __syncthreads();
    }
    g_keys[base + t]        = sk[t];
    g_keys[base + t + 1024] = sk[t + 1024];
}

__global__ void gather_kernel()
{
    int i = blockIdx.x * blockDim.x + threadIdx.x;
    if (i >= PN) return;
    int s = (int)(g_keys[i] & 0xFFFFFFFFu);
    g_pe[i] = g_pe_u[s];
    g_co[i] = g_co_u[s];
    g_cl[i] = g_cl_u[s];
}

// ---------------- tiled rasterizer: 16x16 tiles, ordered compaction + blend ----------------
__global__ __launch_bounds__(256) void raster_kernel(const float* __restrict__ bg,
                                                     float* __restrict__ out)
{
    const int tx = threadIdx.x, ty = threadIdx.y;
    const int tid = ty * 16 + tx;
    const int pxi = blockIdx.x * 16 + tx;
    const int pyi = blockIdx.y * 16 + ty;
    const float pxf = (float)pxi, pyf = (float)pyi;
    const float xmin = (float)(blockIdx.x * 16), xmax = xmin + 15.0f;
    const float ymin = (float)(blockIdx.y * 16), ymax = ymin + 15.0f;

    __shared__ float2 s_xy[256];
    __shared__ float4 s_co[256];
    __shared__ float4 s_cl[256];
    __shared__ int s_wcnt[8];
    __shared__ int s_woff[8];
    __shared__ int s_total;

    float T = 1.0f;
    float ar = 0.0f, ag = 0.0f, ab = 0.0f;
    bool alive = true;

    const int wid = tid >> 5, lane = tid & 31;

    for (int chunk = 0; chunk < PN / 256; chunk++) {
        int g = chunk * 256 + tid;
        float4 pe = g_pe[g];
        // conservative tile-AABB overlap (exact cull: skipped gaussians have alpha==0 here)
        bool hit = (pe.x + pe.z >= xmin) && (pe.x - pe.z <= xmax) &&
                   (pe.y + pe.w >= ymin) && (pe.y - pe.w <= ymax);
        unsigned bal = __ballot_sync(0xffffffffu, hit);
        if (lane == 0) s_wcnt[wid] = __popc(bal);
        __syncthreads();
        if (tid == 0) {
            int s = 0;
            #pragma unroll
            for (int w = 0; w < 8; w++) { s_woff[w] = s; s += s_wcnt[w]; }
            s_total = s;
        }
        __syncthreads();
        if (hit) {
            int slot = s_woff[wid] + __popc(bal & ((1u << lane) - 1u));
            s_xy[slot] = make_float2(pe.x, pe.y);
            s_co[slot] = g_co[g];
            s_cl[slot] = g_cl[g];
        }
        __syncthreads();
        int cnt = s_total;

        if (alive) {
            for (int j = 0; j < cnt; j++) {
                float2 xy = s_xy[j];
                float4 co = s_co[j];
                float dx = xy.x - pxf;
                float dy = xy.y - pyf;
                float power = -0.5f * (co.x*dx*dx + co.z*dy*dy) - co.y*dx*dy;
                if (power > 0.0f) continue;
                float raw = co.w * __expf(power);
                if (raw < (1.0f / 255.0f)) continue;
                float alpha = fminf(0.99f, raw);
                float4 cl = s_cl[j];
                float wgt = alpha * T;
                ar += wgt * cl.x;
                ag += wgt * cl.y;
                ab += wgt * cl.z;
                T *= (1.0f - alpha);
                if (T < 1e-6f) { alive = false; break; }
            }
        }
        // barrier doubles as smem reuse fence; uniform early exit when whole tile saturated
        int nalive = __syncthreads_count(alive ? 1 : 0);
        if (nalive == 0) break;
    }

    int pid = pyi * WD + pxi;
    out[pid]             = ar + T * bg[0];
    out[HD*WD + pid]     = ag + T * bg[1];
    out[2*HD*WD + pid]   = ab + T * bg[2];
}

// ---------------- launch ----------------
extern "C" void kernel_launch(void* const* d_in, const int* in_sizes, int n_in,
                              void* d_out, int out_size)
{
    const float* means  = (const float*)d_in[0];
    const float* cols   = (const float*)d_in[1];
    const float* ops    = (const float*)d_in[2];
    const float* scales = (const float*)d_in[3];
    const float* rots   = (const float*)d_in[4];
    const float* bg     = (const float*)d_in[5];
    const float* Vm     = (const float*)d_in[6];
    const float* Pr     = (const float*)d_in[7];
    float* out = (float*)d_out;

    preprocess_kernel<<<PN/256, 256>>>(means, cols, ops, scales, rots, Vm, Pr);

    // full bitonic network over 8192 keys
    bitonic_local_sort<<<PN/2048, 1024>>>();
    bitonic_global<<<PN/512, 256>>>(4096, 2048);
    bitonic_local_merge<<<PN/2048, 1024>>>(4096);
    bitonic_global<<<PN/512, 256>>>(8192, 4096);
    bitonic_global<<<PN/512, 256>>>(8192, 2048);
    bitonic_local_merge<<<PN/2048, 1024>>>(8192);

    gather_kernel<<<PN/256, 256>>>();

    dim3 grid(WD/16, HD/16), block(16, 16);
    raster_kernel<<<grid, block>>>(bg, out);
}